// round 6
// baseline (speedup 1.0000x reference)
#include <cuda_runtime.h>
#include <cuda_fp16.h>
#include <cstdint>

// ---------------------------------------------------------------------------
// Problem constants
// ---------------------------------------------------------------------------
static constexpr int IN_F   = 512;
static constexpr int OUT_F  = 512;
static constexpr int NEXP   = 8;
static constexpr int NGRP   = 32;
static constexpr int TPG    = 2048;
static constexpr int NTOK   = NGRP * TPG;               // 65536

// Static device scratch: mixed weights fp16, bias fp32, x converted to fp16.
__device__ __half g_w[(size_t)NGRP * OUT_F * IN_F];     // 16.8 MB
__device__ float  g_b[NGRP * OUT_F];
__device__ __half g_x[(size_t)NTOK * IN_F];             // 67 MB

// ---------------------------------------------------------------------------
// Helpers
// ---------------------------------------------------------------------------
__device__ __forceinline__ uint32_t smem_u32(const void* p) {
    uint32_t a;
    asm("{ .reg .u64 t; cvta.to.shared.u64 t, %1; cvt.u32.u64 %0, t; }"
        : "=r"(a) : "l"(p));
    return a;
}

__device__ __forceinline__ uint32_t sw128(uint32_t o) {
    return o ^ ((o >> 3) & 0x70);
}

__device__ __forceinline__ void ldsm4(uint32_t r[4], uint32_t addr) {
    asm volatile("ldmatrix.sync.aligned.m8n8.x4.shared.b16 {%0,%1,%2,%3}, [%4];"
                 : "=r"(r[0]), "=r"(r[1]), "=r"(r[2]), "=r"(r[3]) : "r"(addr));
}

__device__ __forceinline__ void mma16816(float c[4], const uint32_t a[4],
                                         uint32_t b0, uint32_t b1) {
    asm volatile(
        "mma.sync.aligned.m16n8k16.row.col.f32.f16.f16.f32 "
        "{%0,%1,%2,%3}, {%4,%5,%6,%7}, {%8,%9}, {%0,%1,%2,%3};"
        : "+f"(c[0]), "+f"(c[1]), "+f"(c[2]), "+f"(c[3])
        : "r"(a[0]), "r"(a[1]), "r"(a[2]), "r"(a[3]), "r"(b0), "r"(b1));
}

#define CP_ASYNC16(dst, src) \
    asm volatile("cp.async.cg.shared.global [%0], [%1], 16;" :: "r"(dst), "l"(src))
#define CP_COMMIT()  asm volatile("cp.async.commit_group;" ::: "memory")
#define CP_WAIT0()   asm volatile("cp.async.wait_group 0;" ::: "memory")
#define CP_WAIT1()   asm volatile("cp.async.wait_group 1;" ::: "memory")

// ---------------------------------------------------------------------------
// Kernel 1 (fused prep): blocks [0,1024) mix weights -> g_w fp16,
// blocks [1024,3072) convert x -> g_x fp16, blocks [3072,3136) mix bias.
// Independent memory streams overlap inside one launch.
// ---------------------------------------------------------------------------
static constexpr int PREP_MIXW_BLKS = (OUT_F * IN_F) / 256;      // 1024
static constexpr int PREP_CVT_BLKS  = 2048;
static constexpr int PREP_MIXB_BLKS = (NGRP * OUT_F) / 256;      // 64
static constexpr int PREP_GRID = PREP_MIXW_BLKS + PREP_CVT_BLKS + PREP_MIXB_BLKS;

__global__ void __launch_bounds__(256) prep_kernel(const float* __restrict__ x,
                                                   const float* __restrict__ coeff,
                                                   const float* __restrict__ we,
                                                   const float* __restrict__ be,
                                                   const float* __restrict__ ws,
                                                   const float* __restrict__ bs) {
    int b = blockIdx.x;
    int tid = threadIdx.x;
    if (b < PREP_MIXW_BLKS) {
        // ---- mix expert weights ----
        __shared__ float sc[NGRP * NEXP];
        sc[tid] = coeff[tid];                 // 256 == 32*8
        __syncthreads();
        int idx = b * 256 + tid;              // 0 .. 512*512-1
        float w[NEXP];
#pragma unroll
        for (int e = 0; e < NEXP; e++) w[e] = we[(size_t)e * OUT_F * IN_F + idx];
        float shared_w = ws[idx];
#pragma unroll 4
        for (int g = 0; g < NGRP; g++) {
            float acc = shared_w;
#pragma unroll
            for (int e = 0; e < NEXP; e++) acc = fmaf(sc[g * NEXP + e], w[e], acc);
            g_w[(size_t)g * OUT_F * IN_F + idx] = __float2half_rn(acc);
        }
    } else if (b < PREP_MIXW_BLKS + PREP_CVT_BLKS) {
        // ---- convert x fp32 -> fp16 ----
        const float4* src = reinterpret_cast<const float4*>(x);
        uint2* dst = reinterpret_cast<uint2*>(g_x);
        size_t n4 = (size_t)NTOK * IN_F / 4;                 // 8,388,608
        size_t t = (size_t)(b - PREP_MIXW_BLKS) * 256 + tid; // 0 .. 524287
#pragma unroll 4
        for (size_t i = t; i < n4; i += (size_t)PREP_CVT_BLKS * 256) {
            float4 f = src[i];
            __half2 h0 = __floats2half2_rn(f.x, f.y);
            __half2 h1 = __floats2half2_rn(f.z, f.w);
            uint2 u;
            u.x = *reinterpret_cast<uint32_t*>(&h0);
            u.y = *reinterpret_cast<uint32_t*>(&h1);
            dst[i] = u;
        }
    } else {
        // ---- mix bias ----
        int idx = (b - PREP_MIXW_BLKS - PREP_CVT_BLKS) * 256 + tid; // 0..16383
        int g = idx >> 9, o = idx & 511;
        float acc = bs[o];
#pragma unroll
        for (int e = 0; e < NEXP; e++)
            acc = fmaf(coeff[g * NEXP + e], be[e * OUT_F + o], acc);
        g_b[idx] = acc;
    }
}

// ---------------------------------------------------------------------------
// Kernel 2: grouped GEMM  out[g] = x_g @ W_g^T + b_g  via mma.sync (HMMA)
// CTA tile M=128, N=256, K-chunk=64. 512 threads (16 warps), warp tile 32x64.
// All-fp16 smem tiles, ldmatrix for both A and B, 3-stage cp.async pipeline.
// ---------------------------------------------------------------------------
static constexpr int KC = 64;
static constexpr int OFF_BIAS   = 0;                     // 256 f32 = 1 KB
static constexpr int STAGE_SZ   = 16384 + 32768;         // A 16KB + B 32KB (fp16)
static constexpr int OFF_STAGE  = 1024;
static constexpr int SMEM_TOTAL = OFF_STAGE + 3 * STAGE_SZ;   // 148480

__device__ __forceinline__ uint32_t stageA(uint32_t sb, int s) {
    return sb + OFF_STAGE + s * STAGE_SZ;
}
__device__ __forceinline__ uint32_t stageB(uint32_t sb, int s) {
    return sb + OFF_STAGE + s * STAGE_SZ + 16384;
}

// A: 128 rows x 64 fp16 (128B rows, SW128); 1024 16B-chunks, 512 threads
__device__ __forceinline__ void cpA(uint32_t aOffS, const __half* __restrict__ xA,
                                    int kb, int tid) {
#pragma unroll
    for (int it = 0; it < 2; it++) {
        int u = tid + it * 512;
        int row = u >> 3, c16 = u & 7;
        uint32_t dst = aOffS + sw128((uint32_t)(row * 128 + c16 * 16));
        CP_ASYNC16(dst, xA + (size_t)row * IN_F + kb + c16 * 8);
    }
}

// B: 256 rows x 64 fp16, 128B rows, SW128 (2 threads/row, 4x16B each)
__device__ __forceinline__ void cpB(uint32_t bOffS, const __half* __restrict__ Wg,
                                    int kb, int n_base, int tid) {
    int row = tid >> 1, h = tid & 1;
    const __half* src = Wg + (size_t)(n_base + row) * IN_F + kb + h * 32;
#pragma unroll
    for (int j = 0; j < 4; j++) {
        uint32_t dst = bOffS + sw128((uint32_t)(row * 128 + (h * 4 + j) * 16));
        CP_ASYNC16(dst, src + j * 8);
    }
}

__device__ __forceinline__ void compute_chunk(uint32_t aBase, uint32_t bBase,
                                              int wm, int wn, int lane,
                                              float acc[2][8][4]) {
#pragma unroll
    for (int kk = 0; kk < 4; kk++) {
        int c0 = kk * 2;
        uint32_t a[2][4];
#pragma unroll
        for (int mt = 0; mt < 2; mt++) {
            int r = wm * 32 + mt * 16 + (lane & 15);
            int c = c0 + (lane >> 4);
            ldsm4(a[mt], aBase + sw128((uint32_t)(r * 128 + c * 16)));
        }
        uint32_t bb[4][4];
#pragma unroll
        for (int nt = 0; nt < 4; nt++) {
            int r = wn * 64 + nt * 16 + (lane & 7) + ((lane & 16) ? 8 : 0);
            int c = c0 + ((lane >> 3) & 1);
            ldsm4(bb[nt], bBase + sw128((uint32_t)(r * 128 + c * 16)));
        }
#pragma unroll
        for (int mt = 0; mt < 2; mt++)
#pragma unroll
            for (int nt = 0; nt < 4; nt++) {
                mma16816(acc[mt][nt * 2 + 0], a[mt], bb[nt][0], bb[nt][1]);
                mma16816(acc[mt][nt * 2 + 1], a[mt], bb[nt][2], bb[nt][3]);
            }
    }
}

__global__ void __launch_bounds__(512, 1) mole_gemm(float* __restrict__ out) {
    extern __shared__ char smem[];
    uint32_t sb = smem_u32(smem);
    int tid = threadIdx.x, wid = tid >> 5, lane = tid & 31;
    int wm = wid & 3, wn = wid >> 2;          // warp grid 4(m) x 4(n)

    int b = blockIdx.x;
    int ntile = b & 1;            // 2 n-tiles of 256
    int mtile = (b >> 1) & 15;    // 16 m-tiles of 128
    int g     = b >> 5;           // 32 groups
    int m_base = g * TPG + mtile * 128;
    int n_base = ntile * 256;
    const __half* xA = g_x + (size_t)m_base * IN_F;
    const __half* Wg = g_w + (size_t)g * OUT_F * IN_F;

    float* sbias = reinterpret_cast<float*>(smem + OFF_BIAS);
    if (tid < 256) sbias[tid] = g_b[g * OUT_F + n_base + tid];

    float acc[2][8][4];
#pragma unroll
    for (int i = 0; i < 2; i++)
#pragma unroll
        for (int j = 0; j < 8; j++)
#pragma unroll
            for (int l = 0; l < 4; l++) acc[i][j][l] = 0.0f;

    // prologue: stages 0 and 1 in flight
    cpA(stageA(sb, 0), xA, 0, tid);
    cpB(stageB(sb, 0), Wg, 0, n_base, tid);
    CP_COMMIT();
    cpA(stageA(sb, 1), xA, KC, tid);
    cpB(stageB(sb, 1), Wg, KC, n_base, tid);
    CP_COMMIT();

#pragma unroll 1
    for (int k = 0; k < 8; k++) {
        if (k == 7) CP_WAIT0(); else CP_WAIT1();
        __syncthreads();
        if (k + 2 < 8) {
            int s = (k + 2) % 3;
            cpA(stageA(sb, s), xA, (k + 2) * KC, tid);
            cpB(stageB(sb, s), Wg, (k + 2) * KC, n_base, tid);
            CP_COMMIT();
        }
        int cs = k % 3;
        compute_chunk(stageA(sb, cs), stageB(sb, cs), wm, wn, lane, acc);
    }

    // epilogue: direct fragment stores + bias
#pragma unroll
    for (int mt = 0; mt < 2; mt++) {
        int r0 = m_base + wm * 32 + mt * 16 + (lane >> 2);
#pragma unroll
        for (int nt8 = 0; nt8 < 8; nt8++) {
            int cl = wn * 64 + nt8 * 8 + (lane & 3) * 2;
            float bx = sbias[cl], by = sbias[cl + 1];
            float2 v0 = make_float2(acc[mt][nt8][0] + bx, acc[mt][nt8][1] + by);
            float2 v1 = make_float2(acc[mt][nt8][2] + bx, acc[mt][nt8][3] + by);
            *reinterpret_cast<float2*>(out + (size_t)r0 * OUT_F + n_base + cl) = v0;
            *reinterpret_cast<float2*>(out + (size_t)(r0 + 8) * OUT_F + n_base + cl) = v1;
        }
    }
}

// ---------------------------------------------------------------------------
// launch
// ---------------------------------------------------------------------------
extern "C" void kernel_launch(void* const* d_in, const int* in_sizes, int n_in,
                              void* d_out, int out_size) {
    const float* x  = (const float*)d_in[0];
    const float* co = (const float*)d_in[1];
    const float* we = (const float*)d_in[2];
    const float* be = (const float*)d_in[3];
    const float* ws = (const float*)d_in[4];
    const float* bs = (const float*)d_in[5];
    float* out = (float*)d_out;

    cudaFuncSetAttribute(mole_gemm, cudaFuncAttributeMaxDynamicSharedMemorySize,
                         SMEM_TOTAL);

    prep_kernel<<<PREP_GRID, 256>>>(x, co, we, be, ws, bs);
    mole_gemm<<<NGRP * 16 * 2, 512, SMEM_TOTAL>>>(out);
}

// round 7
// speedup vs baseline: 1.1867x; 1.1867x over previous
#include <cuda_runtime.h>
#include <cuda_fp16.h>
#include <cstdint>

// ---------------------------------------------------------------------------
// Problem constants
// ---------------------------------------------------------------------------
static constexpr int IN_F   = 512;
static constexpr int OUT_F  = 512;
static constexpr int NEXP   = 8;
static constexpr int NGRP   = 32;
static constexpr int TPG    = 2048;
static constexpr int NTOK   = NGRP * TPG;               // 65536

// Static device scratch.
// g_xt: A tiles, pre-swizzled fp16. tile id ((g*16+mtile)*8+k), 16 KB each.
// g_wt: B tiles, pre-swizzled fp16. tile id ((g*2+ntile)*8+k), 32 KB each.
__device__ unsigned char g_xt[(size_t)4096 * 16384];    // 67 MB
__device__ unsigned char g_wt[(size_t)512 * 32768];     // 16.8 MB
__device__ float g_b[NGRP * OUT_F];

// ---------------------------------------------------------------------------
// Helpers
// ---------------------------------------------------------------------------
__device__ __forceinline__ uint32_t smem_u32(const void* p) {
    uint32_t a;
    asm("{ .reg .u64 t; cvta.to.shared.u64 t, %1; cvt.u32.u64 %0, t; }"
        : "=r"(a) : "l"(p));
    return a;
}

__device__ __forceinline__ uint32_t sw128(uint32_t o) {
    return o ^ ((o >> 3) & 0x70);
}

__device__ __forceinline__ void ldsm4(uint32_t r[4], uint32_t addr) {
    asm volatile("ldmatrix.sync.aligned.m8n8.x4.shared.b16 {%0,%1,%2,%3}, [%4];"
                 : "=r"(r[0]), "=r"(r[1]), "=r"(r[2]), "=r"(r[3]) : "r"(addr));
}

__device__ __forceinline__ void mma16816(float c[4], const uint32_t a[4],
                                         uint32_t b0, uint32_t b1) {
    asm volatile(
        "mma.sync.aligned.m16n8k16.row.col.f32.f16.f16.f32 "
        "{%0,%1,%2,%3}, {%4,%5,%6,%7}, {%8,%9}, {%0,%1,%2,%3};"
        : "+f"(c[0]), "+f"(c[1]), "+f"(c[2]), "+f"(c[3])
        : "r"(a[0]), "r"(a[1]), "r"(a[2]), "r"(a[3]), "r"(b0), "r"(b1));
}

#define MBARRIER_INIT(mbar, count) \
    asm volatile("mbarrier.init.shared.b64 [%0], %1;" \
        :: "r"((uint32_t)(mbar)), "r"((uint32_t)(count)) : "memory")

#define MBARRIER_EXPECT_TX(mbar, tx) \
    asm volatile("mbarrier.arrive.expect_tx.shared.b64 _, [%0], %1;" \
        :: "r"((uint32_t)(mbar)), "r"((uint32_t)(tx)) : "memory")

#define MBARRIER_WAIT_PARITY(mbar_smem_addr, phase_parity) do {                        \
    uint32_t _mbar = (uint32_t)(mbar_smem_addr);                                       \
    uint32_t _parity = (uint32_t)(phase_parity);                                       \
    uint32_t _done;                                                                    \
    asm volatile(                                                                      \
        "{\n\t.reg .pred p;\n\t"                                                       \
        "mbarrier.try_wait.parity.acquire.cta.shared::cta.b64 p, [%1], %2;\n\t"        \
        "selp.b32 %0, 1, 0, p;\n\t}"                                                   \
        : "=r"(_done) : "r"(_mbar), "r"(_parity) : "memory");                          \
    if (!_done) {                                                                      \
        asm volatile(                                                                  \
            "{\n\t.reg .pred P1;\n\t"                                                  \
            "WAIT_LOOP_%=:\n\t"                                                        \
            "mbarrier.try_wait.parity.acquire.cta.shared::cta.b64 P1, [%0], %1, 0x989680;\n\t" \
            "@P1 bra.uni WAIT_DONE_%=;\n\t"                                            \
            "bra.uni WAIT_LOOP_%=;\n\t"                                                \
            "WAIT_DONE_%=:\n\t}"                                                       \
            :: "r"(_mbar), "r"(_parity) : "memory");                                   \
    }                                                                                  \
} while (0)

// 1D bulk async copy gmem -> smem with mbarrier transaction completion.
// Base sm_90 PTX (SASS UBLKCP) -- no arch-accelerated suffix needed.
#define CP_BULK(dstS, srcG, nbytes, mbar) \
    asm volatile( \
        "cp.async.bulk.shared::cluster.global.mbarrier::complete_tx::bytes " \
        "[%0], [%1], %2, [%3];" \
        :: "r"((uint32_t)(dstS)), "l"(srcG), "r"((uint32_t)(nbytes)), \
           "r"((uint32_t)(mbar)) : "memory")

// ---------------------------------------------------------------------------
// Kernel 1 (fused prep):
//   blocks [0, 4096):       x fp32 -> pre-swizzled fp16 A tiles (g_xt)
//   blocks [4096, 5120):    mix expert weights -> pre-swizzled fp16 B tiles
//   blocks [5120, 5184):    mix bias -> g_b
// ---------------------------------------------------------------------------
static constexpr int PREP_CVT_BLKS  = 4096;
static constexpr int PREP_MIXW_BLKS = (OUT_F * IN_F) / 256;      // 1024
static constexpr int PREP_MIXB_BLKS = (NGRP * OUT_F) / 256;      // 64
static constexpr int PREP_GRID = PREP_CVT_BLKS + PREP_MIXW_BLKS + PREP_MIXB_BLKS;

__global__ void __launch_bounds__(256) prep_kernel(const float* __restrict__ x,
                                                   const float* __restrict__ coeff,
                                                   const float* __restrict__ we,
                                                   const float* __restrict__ be,
                                                   const float* __restrict__ ws,
                                                   const float* __restrict__ bs) {
    int b = blockIdx.x;
    int tid = threadIdx.x;
    if (b < PREP_CVT_BLKS) {
        // ---- one 16 KB A tile: (g, mtile, kc) = tile, 128 rows x 64 fp16 ----
        int t = b;
        int m_base = (t >> 7) * TPG + ((t >> 3) & 15) * 128;
        int kb = (t & 7) * 64;
        unsigned char* tile = g_xt + (size_t)t * 16384;
#pragma unroll
        for (int it = 0; it < 4; it++) {
            int u = tid + it * 256;          // 0..1023 (row, 16B unit)
            int row = u >> 3, c16 = u & 7;
            const float4* src = reinterpret_cast<const float4*>(
                x + (size_t)(m_base + row) * IN_F + kb + c16 * 8);
            float4 f0 = src[0], f1 = src[1];
            __half2 h0 = __floats2half2_rn(f0.x, f0.y);
            __half2 h1 = __floats2half2_rn(f0.z, f0.w);
            __half2 h2 = __floats2half2_rn(f1.x, f1.y);
            __half2 h3 = __floats2half2_rn(f1.z, f1.w);
            uint4 v;
            v.x = *reinterpret_cast<uint32_t*>(&h0);
            v.y = *reinterpret_cast<uint32_t*>(&h1);
            v.z = *reinterpret_cast<uint32_t*>(&h2);
            v.w = *reinterpret_cast<uint32_t*>(&h3);
            *reinterpret_cast<uint4*>(tile + sw128((uint32_t)(row * 128 + c16 * 16))) = v;
        }
    } else if (b < PREP_CVT_BLKS + PREP_MIXW_BLKS) {
        // ---- mix expert weights, write into pre-swizzled B tiles ----
        __shared__ float sc[NGRP * NEXP];
        sc[tid] = coeff[tid];                 // 256 == 32*8
        __syncthreads();
        int idx = (b - PREP_CVT_BLKS) * 256 + tid;   // (o, i) flat
        int o = idx >> 9, i = idx & 511;
        float w[NEXP];
#pragma unroll
        for (int e = 0; e < NEXP; e++) w[e] = we[(size_t)e * OUT_F * IN_F + idx];
        float shared_w = ws[idx];
        // within-tile byte offset (same for all g)
        uint32_t woff = sw128((uint32_t)((o & 255) * 128 + (i & 63) * 2));
        int tile_in_g = (o >> 8) * 8 + (i >> 6);     // ntile*8 + kc
#pragma unroll 4
        for (int g = 0; g < NGRP; g++) {
            float acc = shared_w;
#pragma unroll
            for (int e = 0; e < NEXP; e++) acc = fmaf(sc[g * NEXP + e], w[e], acc);
            size_t tile = (size_t)(g * 16 + tile_in_g) * 32768;
            *reinterpret_cast<__half*>(g_wt + tile + woff) = __float2half_rn(acc);
        }
    } else {
        // ---- mix bias ----
        int idx = (b - PREP_CVT_BLKS - PREP_MIXW_BLKS) * 256 + tid;
        int g = idx >> 9, o = idx & 511;
        float acc = bs[o];
#pragma unroll
        for (int e = 0; e < NEXP; e++)
            acc = fmaf(coeff[g * NEXP + e], be[e * OUT_F + o], acc);
        g_b[idx] = acc;
    }
}

// ---------------------------------------------------------------------------
// Kernel 2: grouped GEMM via mma.sync. CTA tile M=128, N=256, K-chunk=64.
// 512 threads (16 warps), warp tile 32x64. 3-stage cp.async.bulk pipeline:
// 2 bulk copies + 1 expect_tx per chunk, issued by one thread.
// ---------------------------------------------------------------------------
static constexpr int OFF_BIAS  = 0;                      // 1 KB
static constexpr int OFF_MBAR  = 1024;                   // 3 x 8 B
static constexpr int OFF_STAGE = 2048;
static constexpr int STAGE_SZ  = 16384 + 32768;          // A 16KB + B 32KB
static constexpr int SMEM_TOTAL = OFF_STAGE + 3 * STAGE_SZ;   // 149504

__device__ __forceinline__ uint32_t stageA(uint32_t sb, int s) {
    return sb + OFF_STAGE + s * STAGE_SZ;
}
__device__ __forceinline__ uint32_t stageB(uint32_t sb, int s) {
    return sb + OFF_STAGE + s * STAGE_SZ + 16384;
}

__device__ __forceinline__ void compute_chunk(uint32_t aBase, uint32_t bBase,
                                              int wm, int wn, int lane,
                                              float acc[2][8][4]) {
#pragma unroll
    for (int kk = 0; kk < 4; kk++) {
        int c0 = kk * 2;
        uint32_t a[2][4];
#pragma unroll
        for (int mt = 0; mt < 2; mt++) {
            int r = wm * 32 + mt * 16 + (lane & 15);
            int c = c0 + (lane >> 4);
            ldsm4(a[mt], aBase + sw128((uint32_t)(r * 128 + c * 16)));
        }
        uint32_t bb[4][4];
#pragma unroll
        for (int nt = 0; nt < 4; nt++) {
            int r = wn * 64 + nt * 16 + (lane & 7) + ((lane & 16) ? 8 : 0);
            int c = c0 + ((lane >> 3) & 1);
            ldsm4(bb[nt], bBase + sw128((uint32_t)(r * 128 + c * 16)));
        }
#pragma unroll
        for (int mt = 0; mt < 2; mt++)
#pragma unroll
            for (int nt = 0; nt < 4; nt++) {
                mma16816(acc[mt][nt * 2 + 0], a[mt], bb[nt][0], bb[nt][1]);
                mma16816(acc[mt][nt * 2 + 1], a[mt], bb[nt][2], bb[nt][3]);
            }
    }
}

__global__ void __launch_bounds__(512, 1) mole_gemm(float* __restrict__ out) {
    extern __shared__ char smem[];
    uint32_t sb = smem_u32(smem);
    int tid = threadIdx.x, wid = tid >> 5, lane = tid & 31;
    int wm = wid & 3, wn = wid >> 2;          // warp grid 4(m) x 4(n)

    int b = blockIdx.x;
    int ntile = b & 1;            // 2 n-tiles of 256
    int mtile = (b >> 1) & 15;    // 16 m-tiles of 128
    int g     = b >> 5;           // 32 groups
    int m_base = g * TPG + mtile * 128;
    int n_base = ntile * 256;
    const unsigned char* aTiles = g_xt + (size_t)((g * 16 + mtile) * 8) * 16384;
    const unsigned char* bTiles = g_wt + (size_t)((g * 2 + ntile) * 8) * 32768;

    float* sbias = reinterpret_cast<float*>(smem + OFF_BIAS);
    if (tid < 256) sbias[tid] = g_b[g * OUT_F + n_base + tid];

    if (tid == 0) {
        MBARRIER_INIT(sb + OFF_MBAR + 0, 1);
        MBARRIER_INIT(sb + OFF_MBAR + 8, 1);
        MBARRIER_INIT(sb + OFF_MBAR + 16, 1);
    }
    __syncthreads();

    // prologue: chunks 0..2 into stages 0..2
    if (tid == 0) {
#pragma unroll
        for (int k = 0; k < 3; k++) {
            uint32_t mb = sb + OFF_MBAR + k * 8;
            MBARRIER_EXPECT_TX(mb, STAGE_SZ);
            CP_BULK(stageA(sb, k), aTiles + (size_t)k * 16384, 16384, mb);
            CP_BULK(stageB(sb, k), bTiles + (size_t)k * 32768, 32768, mb);
        }
    }

    float acc[2][8][4];
#pragma unroll
    for (int i = 0; i < 2; i++)
#pragma unroll
        for (int j = 0; j < 8; j++)
#pragma unroll
            for (int l = 0; l < 4; l++) acc[i][j][l] = 0.0f;

#pragma unroll 1
    for (int k = 0; k < 8; k++) {
        int s = k % 3;
        MBARRIER_WAIT_PARITY(sb + OFF_MBAR + s * 8, (k / 3) & 1);
        compute_chunk(stageA(sb, s), stageB(sb, s), wm, wn, lane, acc);
        __syncthreads();   // all warps done reading stage s
        if (k + 3 < 8 && tid == 0) {
            uint32_t mb = sb + OFF_MBAR + s * 8;
            MBARRIER_EXPECT_TX(mb, STAGE_SZ);
            CP_BULK(stageA(sb, s), aTiles + (size_t)(k + 3) * 16384, 16384, mb);
            CP_BULK(stageB(sb, s), bTiles + (size_t)(k + 3) * 32768, 32768, mb);
        }
    }

    // epilogue: direct fragment stores + bias
#pragma unroll
    for (int mt = 0; mt < 2; mt++) {
        int r0 = m_base + wm * 32 + mt * 16 + (lane >> 2);
#pragma unroll
        for (int nt8 = 0; nt8 < 8; nt8++) {
            int cl = wn * 64 + nt8 * 8 + (lane & 3) * 2;
            float bx = sbias[cl], by = sbias[cl + 1];
            float2 v0 = make_float2(acc[mt][nt8][0] + bx, acc[mt][nt8][1] + by);
            float2 v1 = make_float2(acc[mt][nt8][2] + bx, acc[mt][nt8][3] + by);
            *reinterpret_cast<float2*>(out + (size_t)r0 * OUT_F + n_base + cl) = v0;
            *reinterpret_cast<float2*>(out + (size_t)(r0 + 8) * OUT_F + n_base + cl) = v1;
        }
    }
}

// ---------------------------------------------------------------------------
// launch
// ---------------------------------------------------------------------------
extern "C" void kernel_launch(void* const* d_in, const int* in_sizes, int n_in,
                              void* d_out, int out_size) {
    const float* x  = (const float*)d_in[0];
    const float* co = (const float*)d_in[1];
    const float* we = (const float*)d_in[2];
    const float* be = (const float*)d_in[3];
    const float* ws = (const float*)d_in[4];
    const float* bs = (const float*)d_in[5];
    float* out = (float*)d_out;

    cudaFuncSetAttribute(mole_gemm, cudaFuncAttributeMaxDynamicSharedMemorySize,
                         SMEM_TOTAL);

    prep_kernel<<<PREP_GRID, 256>>>(x, co, we, be, ws, bs);
    mole_gemm<<<NGRP * 16 * 2, 512, SMEM_TOTAL>>>(out);
}

// round 11
// speedup vs baseline: 1.2585x; 1.0605x over previous
#include <cuda_runtime.h>
#include <cuda_fp16.h>
#include <cstdint>

// ---------------------------------------------------------------------------
// Problem constants
// ---------------------------------------------------------------------------
static constexpr int IN_F   = 512;
static constexpr int OUT_F  = 512;
static constexpr int NEXP   = 8;
static constexpr int NGRP   = 32;
static constexpr int TPG    = 2048;

// Static device scratch.
// g_xt: A tiles, pre-swizzled fp16. tile id ((g*16+mtile)*8+kc), 16 KB each.
// g_wt: B tiles, pre-swizzled fp16. tile id ((g*4+ntile)*8+kc), 16 KB each.
__device__ unsigned char g_xt[(size_t)4096 * 16384];    // 67 MB
__device__ unsigned char g_wt[(size_t)1024 * 16384];    // 16.8 MB
__device__ float g_b[NGRP * OUT_F];

// ---------------------------------------------------------------------------
// Helpers
// ---------------------------------------------------------------------------
__device__ __forceinline__ uint32_t smem_u32(const void* p) {
    uint32_t a;
    asm("{ .reg .u64 t; cvta.to.shared.u64 t, %1; cvt.u32.u64 %0, t; }"
        : "=r"(a) : "l"(p));
    return a;
}

__device__ __forceinline__ uint32_t sw128(uint32_t o) {
    return o ^ ((o >> 3) & 0x70);
}

__device__ __forceinline__ void ldsm4(uint32_t r[4], uint32_t addr) {
    asm volatile("ldmatrix.sync.aligned.m8n8.x4.shared.b16 {%0,%1,%2,%3}, [%4];"
                 : "=r"(r[0]), "=r"(r[1]), "=r"(r[2]), "=r"(r[3]) : "r"(addr));
}

__device__ __forceinline__ void mma16816(float c[4], const uint32_t a[4],
                                         uint32_t b0, uint32_t b1) {
    asm volatile(
        "mma.sync.aligned.m16n8k16.row.col.f32.f16.f16.f32 "
        "{%0,%1,%2,%3}, {%4,%5,%6,%7}, {%8,%9}, {%0,%1,%2,%3};"
        : "+f"(c[0]), "+f"(c[1]), "+f"(c[2]), "+f"(c[3])
        : "r"(a[0]), "r"(a[1]), "r"(a[2]), "r"(a[3]), "r"(b0), "r"(b1));
}

#define MBARRIER_INIT(mbar, count) \
    asm volatile("mbarrier.init.shared.b64 [%0], %1;" \
        :: "r"((uint32_t)(mbar)), "r"((uint32_t)(count)) : "memory")

#define MBARRIER_EXPECT_TX(mbar, tx) \
    asm volatile("mbarrier.arrive.expect_tx.shared.b64 _, [%0], %1;" \
        :: "r"((uint32_t)(mbar)), "r"((uint32_t)(tx)) : "memory")

#define MBARRIER_WAIT_PARITY(mbar_smem_addr, phase_parity) do {                        \
    uint32_t _mbar = (uint32_t)(mbar_smem_addr);                                       \
    uint32_t _parity = (uint32_t)(phase_parity);                                       \
    uint32_t _done;                                                                    \
    asm volatile(                                                                      \
        "{\n\t.reg .pred p;\n\t"                                                       \
        "mbarrier.try_wait.parity.acquire.cta.shared::cta.b64 p, [%1], %2;\n\t"        \
        "selp.b32 %0, 1, 0, p;\n\t}"                                                   \
        : "=r"(_done) : "r"(_mbar), "r"(_parity) : "memory");                          \
    if (!_done) {                                                                      \
        asm volatile(                                                                  \
            "{\n\t.reg .pred P1;\n\t"                                                  \
            "WAIT_LOOP_%=:\n\t"                                                        \
            "mbarrier.try_wait.parity.acquire.cta.shared::cta.b64 P1, [%0], %1, 0x989680;\n\t" \
            "@P1 bra.uni WAIT_DONE_%=;\n\t"                                            \
            "bra.uni WAIT_LOOP_%=;\n\t"                                                \
            "WAIT_DONE_%=:\n\t}"                                                       \
            :: "r"(_mbar), "r"(_parity) : "memory");                                   \
    }                                                                                  \
} while (0)

// 1D bulk async copy gmem -> smem with mbarrier transaction completion.
#define CP_BULK(dstS, srcG, nbytes, mbar) \
    asm volatile( \
        "cp.async.bulk.shared::cluster.global.mbarrier::complete_tx::bytes " \
        "[%0], [%1], %2, [%3];" \
        :: "r"((uint32_t)(dstS)), "l"(srcG), "r"((uint32_t)(nbytes)), \
           "r"((uint32_t)(mbar)) : "memory")

// ---------------------------------------------------------------------------
// Kernel 1 (fused prep):
//   blocks [0, 4096):       x fp32 -> pre-swizzled fp16 A tiles (g_xt)
//   blocks [4096, 5120):    mix expert weights -> pre-swizzled fp16 B tiles
//   blocks [5120, 5184):    mix bias -> g_b
// ---------------------------------------------------------------------------
static constexpr int PREP_CVT_BLKS  = 4096;
static constexpr int PREP_MIXW_BLKS = (OUT_F * IN_F) / 256;      // 1024
static constexpr int PREP_MIXB_BLKS = (NGRP * OUT_F) / 256;      // 64
static constexpr int PREP_GRID = PREP_CVT_BLKS + PREP_MIXW_BLKS + PREP_MIXB_BLKS;

__global__ void __launch_bounds__(256) prep_kernel(const float* __restrict__ x,
                                                   const float* __restrict__ coeff,
                                                   const float* __restrict__ we,
                                                   const float* __restrict__ be,
                                                   const float* __restrict__ ws,
                                                   const float* __restrict__ bs) {
    int b = blockIdx.x;
    int tid = threadIdx.x;
    if (b < PREP_CVT_BLKS) {
        // ---- one 16 KB A tile: (g, mtile, kc), 128 rows x 64 fp16 ----
        int t = b;
        int m_base = (t >> 7) * TPG + ((t >> 3) & 15) * 128;
        int kb = (t & 7) * 64;
        unsigned char* tile = g_xt + (size_t)t * 16384;
#pragma unroll
        for (int it = 0; it < 4; it++) {
            int u = tid + it * 256;          // 0..1023 (row, 16B unit)
            int row = u >> 3, c16 = u & 7;
            const float4* src = reinterpret_cast<const float4*>(
                x + (size_t)(m_base + row) * IN_F + kb + c16 * 8);
            float4 f0 = src[0], f1 = src[1];
            __half2 h0 = __floats2half2_rn(f0.x, f0.y);
            __half2 h1 = __floats2half2_rn(f0.z, f0.w);
            __half2 h2 = __floats2half2_rn(f1.x, f1.y);
            __half2 h3 = __floats2half2_rn(f1.z, f1.w);
            uint4 v;
            v.x = *reinterpret_cast<uint32_t*>(&h0);
            v.y = *reinterpret_cast<uint32_t*>(&h1);
            v.z = *reinterpret_cast<uint32_t*>(&h2);
            v.w = *reinterpret_cast<uint32_t*>(&h3);
            *reinterpret_cast<uint4*>(tile + sw128((uint32_t)(row * 128 + c16 * 16))) = v;
        }
    } else if (b < PREP_CVT_BLKS + PREP_MIXW_BLKS) {
        // ---- mix expert weights into pre-swizzled 16 KB B tiles ----
        __shared__ float sc[NGRP * NEXP];
        sc[tid] = coeff[tid];                 // 256 == 32*8
        __syncthreads();
        int idx = (b - PREP_CVT_BLKS) * 256 + tid;   // (o, i) flat
        int o = idx >> 9, i = idx & 511;
        float w[NEXP];
#pragma unroll
        for (int e = 0; e < NEXP; e++) w[e] = we[(size_t)e * OUT_F * IN_F + idx];
        float shared_w = ws[idx];
        // within-tile byte offset (same for all g): 128 rows x 64 cols fp16
        uint32_t woff = sw128((uint32_t)((o & 127) * 128 + (i & 63) * 2));
        int tile_in_g = (o >> 7) * 8 + (i >> 6);     // ntile*8 + kc
#pragma unroll 4
        for (int g = 0; g < NGRP; g++) {
            float acc = shared_w;
#pragma unroll
            for (int e = 0; e < NEXP; e++) acc = fmaf(sc[g * NEXP + e], w[e], acc);
            size_t tile = (size_t)(g * 32 + tile_in_g) * 16384;
            *reinterpret_cast<__half*>(g_wt + tile + woff) = __float2half_rn(acc);
        }
    } else {
        // ---- mix bias ----
        int idx = (b - PREP_CVT_BLKS - PREP_MIXW_BLKS) * 256 + tid;
        int g = idx >> 9, o = idx & 511;
        float acc = bs[o];
#pragma unroll
        for (int e = 0; e < NEXP; e++)
            acc = fmaf(coeff[g * NEXP + e], be[e * OUT_F + o], acc);
        g_b[idx] = acc;
    }
}

// ---------------------------------------------------------------------------
// Kernel 2: grouped GEMM via mma.sync. CTA tile M=128, N=128, K-chunk=64.
// 256 threads (8 warps: 4m x 2n), warp tile 32x64. 3-stage bulk pipeline.
// 2 CTAs/SM (regs 128 x 512 thr = full RF, smem 97 KB x 2) interleave so the
// tensor pipe stays fed across one CTA's stage barriers.
// ---------------------------------------------------------------------------
static constexpr int OFF_BIAS  = 0;                      // 128 f32 = 512 B
static constexpr int OFF_MBAR  = 512;                    // 3 x 8 B
static constexpr int OFF_STAGE = 1024;
static constexpr int STAGE_SZ  = 16384 + 16384;          // A 16KB + B 16KB
static constexpr int SMEM_TOTAL = OFF_STAGE + 3 * STAGE_SZ;   // 99328

__device__ __forceinline__ uint32_t stageA(uint32_t sb, int s) {
    return sb + OFF_STAGE + s * STAGE_SZ;
}
__device__ __forceinline__ uint32_t stageB(uint32_t sb, int s) {
    return sb + OFF_STAGE + s * STAGE_SZ + 16384;
}

__device__ __forceinline__ void compute_chunk(uint32_t aBase, uint32_t bBase,
                                              int wm, int wn, int lane,
                                              float acc[2][8][4]) {
#pragma unroll
    for (int kk = 0; kk < 4; kk++) {
        int c0 = kk * 2;
        uint32_t a[2][4];
#pragma unroll
        for (int mt = 0; mt < 2; mt++) {
            int r = wm * 32 + mt * 16 + (lane & 15);
            int c = c0 + (lane >> 4);
            ldsm4(a[mt], aBase + sw128((uint32_t)(r * 128 + c * 16)));
        }
        uint32_t bb[4][4];
#pragma unroll
        for (int nt = 0; nt < 4; nt++) {
            int r = wn * 64 + nt * 16 + (lane & 7) + ((lane & 16) ? 8 : 0);
            int c = c0 + ((lane >> 3) & 1);
            ldsm4(bb[nt], bBase + sw128((uint32_t)(r * 128 + c * 16)));
        }
#pragma unroll
        for (int mt = 0; mt < 2; mt++)
#pragma unroll
            for (int nt = 0; nt < 4; nt++) {
                mma16816(acc[mt][nt * 2 + 0], a[mt], bb[nt][0], bb[nt][1]);
                mma16816(acc[mt][nt * 2 + 1], a[mt], bb[nt][2], bb[nt][3]);
            }
    }
}

__global__ void __launch_bounds__(256, 2) mole_gemm(float* __restrict__ out) {
    extern __shared__ char smem[];
    uint32_t sb = smem_u32(smem);
    int tid = threadIdx.x, wid = tid >> 5, lane = tid & 31;
    int wm = wid & 3, wn = wid >> 2;          // warp grid 4(m) x 2(n)

    int b = blockIdx.x;
    int ntile = b & 3;            // 4 n-tiles of 128
    int mtile = (b >> 2) & 15;    // 16 m-tiles of 128
    int g     = b >> 6;           // 32 groups
    int m_base = g * TPG + mtile * 128;
    int n_base = ntile * 128;
    const unsigned char* aTiles = g_xt + (size_t)((g * 16 + mtile) * 8) * 16384;
    const unsigned char* bTiles = g_wt + (size_t)((g * 4 + ntile) * 8) * 16384;

    float* sbias = reinterpret_cast<float*>(smem + OFF_BIAS);
    if (tid < 128) sbias[tid] = g_b[g * OUT_F + n_base + tid];

    if (tid == 0) {
        MBARRIER_INIT(sb + OFF_MBAR + 0, 1);
        MBARRIER_INIT(sb + OFF_MBAR + 8, 1);
        MBARRIER_INIT(sb + OFF_MBAR + 16, 1);
    }
    __syncthreads();

    // prologue: chunks 0..2 into stages 0..2
    if (tid == 0) {
#pragma unroll
        for (int k = 0; k < 3; k++) {
            uint32_t mb = sb + OFF_MBAR + k * 8;
            MBARRIER_EXPECT_TX(mb, STAGE_SZ);
            CP_BULK(stageA(sb, k), aTiles + (size_t)k * 16384, 16384, mb);
            CP_BULK(stageB(sb, k), bTiles + (size_t)k * 16384, 16384, mb);
        }
    }

    float acc[2][8][4];
#pragma unroll
    for (int i = 0; i < 2; i++)
#pragma unroll
        for (int j = 0; j < 8; j++)
#pragma unroll
            for (int l = 0; l < 4; l++) acc[i][j][l] = 0.0f;

#pragma unroll 1
    for (int k = 0; k < 8; k++) {
        int s = k % 3;
        MBARRIER_WAIT_PARITY(sb + OFF_MBAR + s * 8, (k / 3) & 1);
        compute_chunk(stageA(sb, s), stageB(sb, s), wm, wn, lane, acc);
        __syncthreads();   // all warps done reading stage s
        if (k + 3 < 8 && tid == 0) {
            uint32_t mb = sb + OFF_MBAR + s * 8;
            MBARRIER_EXPECT_TX(mb, STAGE_SZ);
            CP_BULK(stageA(sb, s), aTiles + (size_t)(k + 3) * 16384, 16384, mb);
            CP_BULK(stageB(sb, s), bTiles + (size_t)(k + 3) * 16384, 16384, mb);
        }
    }

    // epilogue: direct fragment stores + bias
#pragma unroll
    for (int mt = 0; mt < 2; mt++) {
        int r0 = m_base + wm * 32 + mt * 16 + (lane >> 2);
#pragma unroll
        for (int nt8 = 0; nt8 < 8; nt8++) {
            int cl = wn * 64 + nt8 * 8 + (lane & 3) * 2;
            float bx = sbias[cl], by = sbias[cl + 1];
            float2 v0 = make_float2(acc[mt][nt8][0] + bx, acc[mt][nt8][1] + by);
            float2 v1 = make_float2(acc[mt][nt8][2] + bx, acc[mt][nt8][3] + by);
            *reinterpret_cast<float2*>(out + (size_t)r0 * OUT_F + n_base + cl) = v0;
            *reinterpret_cast<float2*>(out + (size_t)(r0 + 8) * OUT_F + n_base + cl) = v1;
        }
    }
}

// ---------------------------------------------------------------------------
// launch
// ---------------------------------------------------------------------------
extern "C" void kernel_launch(void* const* d_in, const int* in_sizes, int n_in,
                              void* d_out, int out_size) {
    const float* x  = (const float*)d_in[0];
    const float* co = (const float*)d_in[1];
    const float* we = (const float*)d_in[2];
    const float* be = (const float*)d_in[3];
    const float* ws = (const float*)d_in[4];
    const float* bs = (const float*)d_in[5];
    float* out = (float*)d_out;

    cudaFuncSetAttribute(mole_gemm, cudaFuncAttributeMaxDynamicSharedMemorySize,
                         SMEM_TOTAL);

    prep_kernel<<<PREP_GRID, 256>>>(x, co, we, be, ws, bs);
    mole_gemm<<<NGRP * 16 * 4, 256, SMEM_TOTAL>>>(out);
}

// round 13
// speedup vs baseline: 1.2791x; 1.0163x over previous
#include <cuda_runtime.h>
#include <cuda_fp16.h>
#include <cstdint>

// ---------------------------------------------------------------------------
// Problem constants
// ---------------------------------------------------------------------------
static constexpr int IN_F   = 512;
static constexpr int OUT_F  = 512;
static constexpr int NEXP   = 8;
static constexpr int NGRP   = 32;
static constexpr int TPG    = 2048;

// Static device scratch.
// g_xt: A tiles, pre-swizzled fp16. tile id ((g*16+mtile)*8+kc), 16 KB each.
// g_wt: B tiles, pre-swizzled fp16. tile id ((g*4+ntile)*8+kc), 16 KB each.
__device__ unsigned char g_xt[(size_t)4096 * 16384];    // 67 MB
__device__ unsigned char g_wt[(size_t)1024 * 16384];    // 16.8 MB
__device__ float g_b[NGRP * OUT_F];

// ---------------------------------------------------------------------------
// Helpers
// ---------------------------------------------------------------------------
__device__ __forceinline__ uint32_t smem_u32(const void* p) {
    uint32_t a;
    asm("{ .reg .u64 t; cvta.to.shared.u64 t, %1; cvt.u32.u64 %0, t; }"
        : "=r"(a) : "l"(p));
    return a;
}

__device__ __forceinline__ uint32_t sw128(uint32_t o) {
    return o ^ ((o >> 3) & 0x70);
}

__device__ __forceinline__ void ldsm4(uint32_t r[4], uint32_t addr) {
    asm volatile("ldmatrix.sync.aligned.m8n8.x4.shared.b16 {%0,%1,%2,%3}, [%4];"
                 : "=r"(r[0]), "=r"(r[1]), "=r"(r[2]), "=r"(r[3]) : "r"(addr));
}

__device__ __forceinline__ void mma16816(float c[4], const uint32_t a[4],
                                         uint32_t b0, uint32_t b1) {
    asm volatile(
        "mma.sync.aligned.m16n8k16.row.col.f32.f16.f16.f32 "
        "{%0,%1,%2,%3}, {%4,%5,%6,%7}, {%8,%9}, {%0,%1,%2,%3};"
        : "+f"(c[0]), "+f"(c[1]), "+f"(c[2]), "+f"(c[3])
        : "r"(a[0]), "r"(a[1]), "r"(a[2]), "r"(a[3]), "r"(b0), "r"(b1));
}

#define MBARRIER_INIT(mbar, count) \
    asm volatile("mbarrier.init.shared.b64 [%0], %1;" \
        :: "r"((uint32_t)(mbar)), "r"((uint32_t)(count)) : "memory")

#define MBARRIER_ARRIVE(mbar) \
    asm volatile("mbarrier.arrive.shared.b64 _, [%0];" \
        :: "r"((uint32_t)(mbar)) : "memory")

#define MBARRIER_EXPECT_TX(mbar, tx) \
    asm volatile("mbarrier.arrive.expect_tx.shared.b64 _, [%0], %1;" \
        :: "r"((uint32_t)(mbar)), "r"((uint32_t)(tx)) : "memory")

#define MBARRIER_WAIT_PARITY(mbar_smem_addr, phase_parity) do {                        \
    uint32_t _mbar = (uint32_t)(mbar_smem_addr);                                       \
    uint32_t _parity = (uint32_t)(phase_parity);                                       \
    uint32_t _done;                                                                    \
    asm volatile(                                                                      \
        "{\n\t.reg .pred p;\n\t"                                                       \
        "mbarrier.try_wait.parity.acquire.cta.shared::cta.b64 p, [%1], %2;\n\t"        \
        "selp.b32 %0, 1, 0, p;\n\t}"                                                   \
        : "=r"(_done) : "r"(_mbar), "r"(_parity) : "memory");                          \
    if (!_done) {                                                                      \
        asm volatile(                                                                  \
            "{\n\t.reg .pred P1;\n\t"                                                  \
            "WAIT_LOOP_%=:\n\t"                                                        \
            "mbarrier.try_wait.parity.acquire.cta.shared::cta.b64 P1, [%0], %1, 0x989680;\n\t" \
            "@P1 bra.uni WAIT_DONE_%=;\n\t"                                            \
            "bra.uni WAIT_LOOP_%=;\n\t"                                                \
            "WAIT_DONE_%=:\n\t}"                                                       \
            :: "r"(_mbar), "r"(_parity) : "memory");                                   \
    }                                                                                  \
} while (0)

// 1D bulk async copy gmem -> smem with mbarrier transaction completion.
#define CP_BULK(dstS, srcG, nbytes, mbar) \
    asm volatile( \
        "cp.async.bulk.shared::cluster.global.mbarrier::complete_tx::bytes " \
        "[%0], [%1], %2, [%3];" \
        :: "r"((uint32_t)(dstS)), "l"(srcG), "r"((uint32_t)(nbytes)), \
           "r"((uint32_t)(mbar)) : "memory")

// ---------------------------------------------------------------------------
// Kernel 1 (fused prep):
//   blocks [0, 4096):       x fp32 -> pre-swizzled fp16 A tiles (g_xt)
//   blocks [4096, 5120):    mix expert weights -> pre-swizzled fp16 B tiles
//   blocks [5120, 5184):    mix bias -> g_b
// ---------------------------------------------------------------------------
static constexpr int PREP_CVT_BLKS  = 4096;
static constexpr int PREP_MIXW_BLKS = (OUT_F * IN_F) / 256;      // 1024
static constexpr int PREP_MIXB_BLKS = (NGRP * OUT_F) / 256;      // 64
static constexpr int PREP_GRID = PREP_CVT_BLKS + PREP_MIXW_BLKS + PREP_MIXB_BLKS;

__global__ void __launch_bounds__(256) prep_kernel(const float* __restrict__ x,
                                                   const float* __restrict__ coeff,
                                                   const float* __restrict__ we,
                                                   const float* __restrict__ be,
                                                   const float* __restrict__ ws,
                                                   const float* __restrict__ bs) {
    int b = blockIdx.x;
    int tid = threadIdx.x;
    if (b < PREP_CVT_BLKS) {
        // ---- one 16 KB A tile: (g, mtile, kc), 128 rows x 64 fp16 ----
        int t = b;
        int m_base = (t >> 7) * TPG + ((t >> 3) & 15) * 128;
        int kb = (t & 7) * 64;
        unsigned char* tile = g_xt + (size_t)t * 16384;
#pragma unroll
        for (int it = 0; it < 4; it++) {
            int u = tid + it * 256;          // 0..1023 (row, 16B unit)
            int row = u >> 3, c16 = u & 7;
            const float4* src = reinterpret_cast<const float4*>(
                x + (size_t)(m_base + row) * IN_F + kb + c16 * 8);
            float4 f0 = src[0], f1 = src[1];
            __half2 h0 = __floats2half2_rn(f0.x, f0.y);
            __half2 h1 = __floats2half2_rn(f0.z, f0.w);
            __half2 h2 = __floats2half2_rn(f1.x, f1.y);
            __half2 h3 = __floats2half2_rn(f1.z, f1.w);
            uint4 v;
            v.x = *reinterpret_cast<uint32_t*>(&h0);
            v.y = *reinterpret_cast<uint32_t*>(&h1);
            v.z = *reinterpret_cast<uint32_t*>(&h2);
            v.w = *reinterpret_cast<uint32_t*>(&h3);
            *reinterpret_cast<uint4*>(tile + sw128((uint32_t)(row * 128 + c16 * 16))) = v;
        }
    } else if (b < PREP_CVT_BLKS + PREP_MIXW_BLKS) {
        // ---- mix expert weights into pre-swizzled 16 KB B tiles ----
        __shared__ float sc[NGRP * NEXP];
        sc[tid] = coeff[tid];                 // 256 == 32*8
        __syncthreads();
        int idx = (b - PREP_CVT_BLKS) * 256 + tid;   // (o, i) flat
        int o = idx >> 9, i = idx & 511;
        float w[NEXP];
#pragma unroll
        for (int e = 0; e < NEXP; e++) w[e] = we[(size_t)e * OUT_F * IN_F + idx];
        float shared_w = ws[idx];
        // within-tile byte offset (same for all g): 128 rows x 64 cols fp16
        uint32_t woff = sw128((uint32_t)((o & 127) * 128 + (i & 63) * 2));
        int tile_in_g = (o >> 7) * 8 + (i >> 6);     // ntile*8 + kc
#pragma unroll 4
        for (int g = 0; g < NGRP; g++) {
            float acc = shared_w;
#pragma unroll
            for (int e = 0; e < NEXP; e++) acc = fmaf(sc[g * NEXP + e], w[e], acc);
            size_t tile = (size_t)(g * 32 + tile_in_g) * 16384;
            *reinterpret_cast<__half*>(g_wt + tile + woff) = __float2half_rn(acc);
        }
    } else {
        // ---- mix bias ----
        int idx = (b - PREP_CVT_BLKS - PREP_MIXW_BLKS) * 256 + tid;
        int g = idx >> 9, o = idx & 511;
        float acc = bs[o];
#pragma unroll
        for (int e = 0; e < NEXP; e++)
            acc = fmaf(coeff[g * NEXP + e], be[e * OUT_F + o], acc);
        g_b[idx] = acc;
    }
}

// ---------------------------------------------------------------------------
// Kernel 2: grouped GEMM via mma.sync. CTA tile M=128, N=128, K-chunk=64.
// 256 threads (8 warps: 4m x 2n), warp tile 32x64. 3-stage bulk pipeline,
// 2 CTAs/SM. Warp-decoupled: per-stage full/empty mbarriers instead of
// __syncthreads so fast warps run ahead and keep the HMMA pipe fed.
// ---------------------------------------------------------------------------
static constexpr int OFF_BIAS  = 0;                      // 128 f32 = 512 B
static constexpr int OFF_FULL  = 512;                    // 3 x 8 B
static constexpr int OFF_EMPTY = 512 + 24;               // 3 x 8 B
static constexpr int OFF_STAGE = 1024;
static constexpr int STAGE_SZ  = 16384 + 16384;          // A 16KB + B 16KB
static constexpr int SMEM_TOTAL = OFF_STAGE + 3 * STAGE_SZ;   // 99328

__device__ __forceinline__ uint32_t stageA(uint32_t sb, int s) {
    return sb + OFF_STAGE + s * STAGE_SZ;
}
__device__ __forceinline__ uint32_t stageB(uint32_t sb, int s) {
    return sb + OFF_STAGE + s * STAGE_SZ + 16384;
}

__device__ __forceinline__ void compute_chunk(uint32_t aBase, uint32_t bBase,
                                              int wm, int wn, int lane,
                                              float acc[2][8][4]) {
#pragma unroll
    for (int kk = 0; kk < 4; kk++) {
        int c0 = kk * 2;
        uint32_t a[2][4];
#pragma unroll
        for (int mt = 0; mt < 2; mt++) {
            int r = wm * 32 + mt * 16 + (lane & 15);
            int c = c0 + (lane >> 4);
            ldsm4(a[mt], aBase + sw128((uint32_t)(r * 128 + c * 16)));
        }
        uint32_t bb[4][4];
#pragma unroll
        for (int nt = 0; nt < 4; nt++) {
            int r = wn * 64 + nt * 16 + (lane & 7) + ((lane & 16) ? 8 : 0);
            int c = c0 + ((lane >> 3) & 1);
            ldsm4(bb[nt], bBase + sw128((uint32_t)(r * 128 + c * 16)));
        }
#pragma unroll
        for (int mt = 0; mt < 2; mt++)
#pragma unroll
            for (int nt = 0; nt < 4; nt++) {
                mma16816(acc[mt][nt * 2 + 0], a[mt], bb[nt][0], bb[nt][1]);
                mma16816(acc[mt][nt * 2 + 1], a[mt], bb[nt][2], bb[nt][3]);
            }
    }
}

__global__ void __launch_bounds__(256, 2) mole_gemm(float* __restrict__ out) {
    extern __shared__ char smem[];
    uint32_t sb = smem_u32(smem);
    int tid = threadIdx.x, wid = tid >> 5, lane = tid & 31;
    int wm = wid & 3, wn = wid >> 2;          // warp grid 4(m) x 2(n)

    int b = blockIdx.x;
    int ntile = b & 3;            // 4 n-tiles of 128
    int mtile = (b >> 2) & 15;    // 16 m-tiles of 128
    int g     = b >> 6;           // 32 groups
    int m_base = g * TPG + mtile * 128;
    int n_base = ntile * 128;
    const unsigned char* aTiles = g_xt + (size_t)((g * 16 + mtile) * 8) * 16384;
    const unsigned char* bTiles = g_wt + (size_t)((g * 4 + ntile) * 8) * 16384;

    float* sbias = reinterpret_cast<float*>(smem + OFF_BIAS);
    if (tid < 128) sbias[tid] = g_b[g * OUT_F + n_base + tid];

    if (tid == 0) {
#pragma unroll
        for (int s = 0; s < 3; s++) {
            MBARRIER_INIT(sb + OFF_FULL + s * 8, 1);    // tx-tracked
            MBARRIER_INIT(sb + OFF_EMPTY + s * 8, 8);   // one arrive per warp
        }
    }
    __syncthreads();

    // prologue: chunks 0..2 into stages 0..2
    if (tid == 0) {
#pragma unroll
        for (int k = 0; k < 3; k++) {
            uint32_t mb = sb + OFF_FULL + k * 8;
            MBARRIER_EXPECT_TX(mb, STAGE_SZ);
            CP_BULK(stageA(sb, k), aTiles + (size_t)k * 16384, 16384, mb);
            CP_BULK(stageB(sb, k), bTiles + (size_t)k * 16384, 16384, mb);
        }
    }

    float acc[2][8][4];
#pragma unroll
    for (int i = 0; i < 2; i++)
#pragma unroll
        for (int j = 0; j < 8; j++)
#pragma unroll
            for (int l = 0; l < 4; l++) acc[i][j][l] = 0.0f;

#pragma unroll 1
    for (int k = 0; k < 8; k++) {
        int s = k % 3;
        int ph = (k / 3) & 1;
        MBARRIER_WAIT_PARITY(sb + OFF_FULL + s * 8, ph);
        compute_chunk(stageA(sb, s), stageB(sb, s), wm, wn, lane, acc);
        // ldmatrix is warp-synchronous: all lanes' reads of stage s are done.
        if (lane == 0) MBARRIER_ARRIVE(sb + OFF_EMPTY + s * 8);
        if (k + 3 < 8 && tid == 0) {
            // wait until all 8 warps released stage s, then refill it
            MBARRIER_WAIT_PARITY(sb + OFF_EMPTY + s * 8, ph);
            uint32_t mb = sb + OFF_FULL + s * 8;
            MBARRIER_EXPECT_TX(mb, STAGE_SZ);
            CP_BULK(stageA(sb, s), aTiles + (size_t)(k + 3) * 16384, 16384, mb);
            CP_BULK(stageB(sb, s), bTiles + (size_t)(k + 3) * 16384, 16384, mb);
        }
    }

    // epilogue: direct fragment stores + bias
#pragma unroll
    for (int mt = 0; mt < 2; mt++) {
        int r0 = m_base + wm * 32 + mt * 16 + (lane >> 2);
#pragma unroll
        for (int nt8 = 0; nt8 < 8; nt8++) {
            int cl = wn * 64 + nt8 * 8 + (lane & 3) * 2;
            float bx = sbias[cl], by = sbias[cl + 1];
            float2 v0 = make_float2(acc[mt][nt8][0] + bx, acc[mt][nt8][1] + by);
            float2 v1 = make_float2(acc[mt][nt8][2] + bx, acc[mt][nt8][3] + by);
            *reinterpret_cast<float2*>(out + (size_t)r0 * OUT_F + n_base + cl) = v0;
            *reinterpret_cast<float2*>(out + (size_t)(r0 + 8) * OUT_F + n_base + cl) = v1;
        }
    }
}

// ---------------------------------------------------------------------------
// launch
// ---------------------------------------------------------------------------
extern "C" void kernel_launch(void* const* d_in, const int* in_sizes, int n_in,
                              void* d_out, int out_size) {
    const float* x  = (const float*)d_in[0];
    const float* co = (const float*)d_in[1];
    const float* we = (const float*)d_in[2];
    const float* be = (const float*)d_in[3];
    const float* ws = (const float*)d_in[4];
    const float* bs = (const float*)d_in[5];
    float* out = (float*)d_out;

    cudaFuncSetAttribute(mole_gemm, cudaFuncAttributeMaxDynamicSharedMemorySize,
                         SMEM_TOTAL);

    prep_kernel<<<PREP_GRID, 256>>>(x, co, we, be, ws, bs);
    mole_gemm<<<NGRP * 16 * 4, 256, SMEM_TOTAL>>>(out);
}